// round 16
// baseline (speedup 1.0000x reference)
#include <cuda_runtime.h>
#include <cuda_bf16.h>
#include <math.h>
#include <stdint.h>

// ============================================================================
// SoftVectorQuantizer via mma.sync fp16 (m16n8k16, fp32 accum), flash-style.
// z[8,64,64,64] f32, embedding[4096,64] f32.
// out = concat(z_q[2097152], entropy(=0), indices[32768] as f32)
//
// Dual-LDG-stream build (evolves R15's barrier-free streaming, 124.9us):
//  - BOTH K (GEMM1) and pre-transposed V (GEMM2) B-fragments are LDG.128
//    streamed from global in step-contiguous layouts. The 16 movmatrix ops
//    per warp-step are GONE (they ran on the L1tex/LDSM pipe at ~50% and sat
//    on the load->transpose->MMA critical path).
//  - top-2 bookkeeping deferred one step (operates on register-resident S of
//    the previous step) to cover in-step LDG latency with independent work.
//  - NO smem tiles, NO cp.async, NO mainloop barriers.
//  - ex2.approx.f16x2 with softmax shift m=0.6 (cancels in final l2norm)
//  - 512 CTAs x 128 thr, 16 rows/warp, 4 CTAs/SM
//  - fp16 top-2 + exact fp32 argmax refine fused in the tail
// ============================================================================

#define N_E     4096
#define D       64
#define HW      4096
#define NZ      2097152
#define NROWS   32768
#define CTAS    512          // 64 rows per CTA
#define THREADS 128          // 4 warps x 16 rows
#define NT      64           // embedding tiles of 64
#define NSTEP   256          // NT * 4 pi-groups
#define CE      20.60992529f // log2(e)/0.07
#define CM      12.36595517f // 0.6 * CE  (softmax shift m = 0.6)

__device__ float    g_embn[N_E * D];      // normalized embedding (refine)
__device__ uint32_t g_kf[NT * 2048];      // fp16 K B-frags, step-contiguous
__device__ uint16_t g_vf[NT * 4096];      // fp16 V B-frags (pre-transposed), step-contiguous

__device__ __forceinline__ uint32_t ex2_h2(uint32_t h) {
    uint32_t r; asm("ex2.approx.f16x2 %0, %1;" : "=r"(r) : "r"(h)); return r;
}
__device__ __forceinline__ uint32_t pack_h2(float lo, float hi) {
    uint32_t r; asm("cvt.rn.f16x2.f32 %0, %1, %2;" : "=r"(r) : "f"(hi), "f"(lo));
    return r;
}
__device__ __forceinline__ void mma_f16(float c[4], const uint32_t a[4],
                                        uint32_t b0, uint32_t b1) {
    asm volatile(
        "mma.sync.aligned.m16n8k16.row.col.f32.f16.f16.f32 "
        "{%0,%1,%2,%3},{%4,%5,%6,%7},{%8,%9},{%0,%1,%2,%3};"
        : "+f"(c[0]), "+f"(c[1]), "+f"(c[2]), "+f"(c[3])
        : "r"(a[0]), "r"(a[1]), "r"(a[2]), "r"(a[3]), "r"(b0), "r"(b1));
}

// K-frag half-index: step s=(tile*4+pi) occupies uint4 range [s*128, s*128+128).
// uint4 j in 0..3 at [s*128 + j*32 + lane] = b-regs for (nih=j>>1, kp=j&1).
__device__ __forceinline__ int kf_hidx(int e, int d) {
    return ((((e >> 3) * 2 + (d >> 5)) * 32 + (e & 7) * 4 + ((d >> 1) & 3)) * 8)
           + ((d >> 4) & 1) * 4 + ((d >> 3) & 1) * 2 + (d & 1);
}
// V-frag half-index (pre-transposed, step-contiguous): step s=(tile*4+pi),
// uint4 j=dp at [s*128 + dp*32 + lane_v]; lane_v=(d&7)*4+((e>>1)&3);
// components: x/y = b0/b1 of n-chunk 2dp? no: x,y feed o[2dp], z,w feed o[2dp+1].
__device__ __forceinline__ int vf_hidx(int e, int d) {
    int pi = (e >> 4) & 3, dp = d >> 4;
    int u4 = (pi * 4 + dp) * 32 + (d & 7) * 4 + ((e >> 1) & 3);
    return u4 * 8 + ((d >> 3) & 1) * 4 + ((e >> 3) & 1) * 2 + (e & 1);
}

// ---------------------------------------------------------------------------
// prep: normalize embedding rows + scatter fp16 K and V B-fragments (once)
// ---------------------------------------------------------------------------
__global__ void prep_kernel(const float* __restrict__ emb) {
    int e = blockIdx.x * 4 + (threadIdx.x >> 5);
    int lane = threadIdx.x & 31;
    float2 v = reinterpret_cast<const float2*>(emb + (size_t)e * D)[lane];
    float s = v.x * v.x + v.y * v.y;
    #pragma unroll
    for (int o = 16; o; o >>= 1) s += __shfl_xor_sync(0xffffffffu, s, o);
    float inv = 1.0f / fmaxf(sqrtf(s), 1e-12f);
    float2 r; r.x = v.x * inv; r.y = v.y * inv;
    reinterpret_cast<float2*>(g_embn + (size_t)e * D)[lane] = r;

    int tile = e >> 6, el = e & 63;
    int d0 = 2 * lane, d1 = 2 * lane + 1;
    __half h0 = __float2half_rn(r.x), h1 = __float2half_rn(r.y);
    uint16_t u0 = *reinterpret_cast<uint16_t*>(&h0);
    uint16_t u1 = *reinterpret_cast<uint16_t*>(&h1);
    g_kf[tile * 2048 + (kf_hidx(el, d0) >> 1)] =
        (uint32_t)u0 | ((uint32_t)u1 << 16);
    g_vf[tile * 4096 + vf_hidx(el, d0)] = u0;
    g_vf[tile * 4096 + vf_hidx(el, d1)] = u1;
}

// ---------------------------------------------------------------------------
// main fused kernel (barrier-free, dual-LDG-stream mainloop)
// ---------------------------------------------------------------------------
__global__ void __launch_bounds__(THREADS, 4)
svq_main_kernel(const float* __restrict__ z, float* __restrict__ out) {
    __shared__ int s_cand[64][2];  // argmax candidates (epilogue only)

    const int tid  = threadIdx.x;
    const int w    = tid >> 5;
    const int lane = tid & 31;
    const int q    = lane & 3;
    const int r    = lane >> 2;
    const unsigned FULL = 0xffffffffu;

    const uint4* gk = reinterpret_cast<const uint4*>(g_kf) + lane;
    const uint4* gv = reinterpret_cast<const uint4*>(g_vf) + lane;

    // ---- Q: 16 rows/warp, l2-normalize, fp16 A-frags ----
    const int n0  = blockIdx.x * 64;          // first row of this CTA
    const int bb  = n0 >> 12;
    const int hw0 = n0 & (HW - 1);
    const float* zbase = z + (size_t)bb * D * HW + hw0;
    const int wrow = w * 16;                  // warp's first row (CTA-local)

    uint32_t qa[4][4];
    {
        float zq[4][4][2];
        float ssq[2] = {0.f, 0.f};
        #pragma unroll
        for (int ks = 0; ks < 4; ks++)
            #pragma unroll
            for (int a = 0; a < 4; a++) {
                int row = wrow + r + (a & 1) * 8;
                int k   = ks * 16 + 2 * q + ((a & 2) ? 8 : 0);
                float v0 = zbase[(size_t)k * HW + row];
                float v1 = zbase[(size_t)(k + 1) * HW + row];
                zq[ks][a][0] = v0;
                zq[ks][a][1] = v1;
                ssq[a & 1] += v0 * v0 + v1 * v1;
            }
        #pragma unroll
        for (int s = 0; s < 2; s++) {
            ssq[s] += __shfl_xor_sync(FULL, ssq[s], 1);
            ssq[s] += __shfl_xor_sync(FULL, ssq[s], 2);
            ssq[s] = 1.0f / fmaxf(sqrtf(ssq[s]), 1e-12f);
        }
        #pragma unroll
        for (int ks = 0; ks < 4; ks++)
            #pragma unroll
            for (int a = 0; a < 4; a++) {
                float sc = ssq[a & 1];
                qa[ks][a] = pack_h2(zq[ks][a][0] * sc, zq[ks][a][1] * sc);
            }
    }

    float o[8][4];
    #pragma unroll
    for (int di = 0; di < 8; di++)
        #pragma unroll
        for (int c = 0; c < 4; c++) o[di][c] = 0.f;
    float m1[2] = {-1e30f, -1e30f}, m2[2] = {-1e30f, -1e30f};
    int   i1[2] = {0, 0}, i2[2] = {0, 0};

    // previous-step S values for deferred top-2 (init -inf: gates never fire)
    float sp[2][4];
    #pragma unroll
    for (int nih = 0; nih < 2; nih++)
        #pragma unroll
        for (int c = 0; c < 4; c++) sp[nih][c] = -1e30f;

    // ---- barrier-free mainloop: 256 steps, dual LDG streams ----
    #pragma unroll 2
    for (int step = 0; step < NSTEP; step++) {
        // loads for CURRENT step (latency covered by deferred top-2 below,
        // and by cross-iteration hoisting from unroll 2)
        uint4 kb[4], vb[4];
        #pragma unroll
        for (int j = 0; j < 4; j++) {
            kb[j] = gk[step * 128 + j * 32];
            vb[j] = gv[step * 128 + j * 32];
        }

        // deferred top-2 on previous step's S (independent of the loads)
        #pragma unroll
        for (int nih = 0; nih < 2; nih++)
            #pragma unroll
            for (int slot = 0; slot < 2; slot++) {
                float s0 = sp[nih][slot * 2], s1 = sp[nih][slot * 2 + 1];
                if (fmaxf(s0, s1) > m2[slot]) {
                    int col0 = (step - 1) * 16 + nih * 8 + 2 * q;
                    if (s0 > m2[slot]) {
                        if (s0 > m1[slot]) {
                            m2[slot] = m1[slot]; i2[slot] = i1[slot];
                            m1[slot] = s0;       i1[slot] = col0;
                        } else { m2[slot] = s0; i2[slot] = col0; }
                    }
                    if (s1 > m2[slot]) {
                        if (s1 > m1[slot]) {
                            m2[slot] = m1[slot]; i2[slot] = i1[slot];
                            m1[slot] = s1;       i1[slot] = col0 + 1;
                        } else { m2[slot] = s1; i2[slot] = col0 + 1; }
                    }
                }
            }

        // GEMM1: S chunks (16 embeddings)
        float s[2][4];
        #pragma unroll
        for (int nih = 0; nih < 2; nih++) {
            #pragma unroll
            for (int c = 0; c < 4; c++) s[nih][c] = 0.f;
            mma_f16(s[nih], qa[0], kb[nih * 2].x, kb[nih * 2].y);
            mma_f16(s[nih], qa[1], kb[nih * 2].z, kb[nih * 2].w);
            mma_f16(s[nih], qa[2], kb[nih * 2 + 1].x, kb[nih * 2 + 1].y);
            mma_f16(s[nih], qa[3], kb[nih * 2 + 1].z, kb[nih * 2 + 1].w);
        }
        // exp: fp32 fma -> f16x2 pack -> one MUFU per pair (shift m=0.6)
        uint32_t a[4];
        #pragma unroll
        for (int nih = 0; nih < 2; nih++) {
            float t0 = fmaf(s[nih][0], CE, -CM);
            float t1 = fmaf(s[nih][1], CE, -CM);
            float t2 = fmaf(s[nih][2], CE, -CM);
            float t3 = fmaf(s[nih][3], CE, -CM);
            a[nih * 2 + 0] = ex2_h2(pack_h2(t0, t1));
            a[nih * 2 + 1] = ex2_h2(pack_h2(t2, t3));
            // save for next step's deferred top-2
            sp[nih][0] = s[nih][0]; sp[nih][1] = s[nih][1];
            sp[nih][2] = s[nih][2]; sp[nih][3] = s[nih][3];
        }
        // GEMM2: O += P(k16=e) * V  (pre-transposed V, straight from LDG)
        #pragma unroll
        for (int dp = 0; dp < 4; dp++) {
            mma_f16(o[2 * dp],     a, vb[dp].x, vb[dp].y);
            mma_f16(o[2 * dp + 1], a, vb[dp].z, vb[dp].w);
        }
    }

    // final top-2 flush for the last step
    #pragma unroll
    for (int nih = 0; nih < 2; nih++)
        #pragma unroll
        for (int slot = 0; slot < 2; slot++) {
            float s0 = sp[nih][slot * 2], s1 = sp[nih][slot * 2 + 1];
            if (fmaxf(s0, s1) > m2[slot]) {
                int col0 = (NSTEP - 1) * 16 + nih * 8 + 2 * q;
                if (s0 > m2[slot]) {
                    if (s0 > m1[slot]) {
                        m2[slot] = m1[slot]; i2[slot] = i1[slot];
                        m1[slot] = s0;       i1[slot] = col0;
                    } else { m2[slot] = s0; i2[slot] = col0; }
                }
                if (s1 > m2[slot]) {
                    if (s1 > m1[slot]) {
                        m2[slot] = m1[slot]; i2[slot] = i1[slot];
                        m1[slot] = s1;       i1[slot] = col0 + 1;
                    } else { m2[slot] = s1; i2[slot] = col0 + 1; }
                }
            }
        }

    // ---- O: per-row l2norm + store ----
    {
        float oss[2] = {0.f, 0.f};
        #pragma unroll
        for (int di = 0; di < 8; di++) {
            oss[0] += o[di][0] * o[di][0] + o[di][1] * o[di][1];
            oss[1] += o[di][2] * o[di][2] + o[di][3] * o[di][3];
        }
        #pragma unroll
        for (int s = 0; s < 2; s++) {
            oss[s] += __shfl_xor_sync(FULL, oss[s], 1);
            oss[s] += __shfl_xor_sync(FULL, oss[s], 2);
            oss[s] = 1.0f / fmaxf(sqrtf(oss[s]), 1e-12f);
        }
        float* ob = out + (size_t)bb * D * HW + hw0;
        #pragma unroll
        for (int di = 0; di < 8; di++) {
            int d0 = di * 8 + 2 * q;
            int rl = wrow + r, rh = rl + 8;
            ob[(size_t)d0 * HW + rl]       = o[di][0] * oss[0];
            ob[(size_t)(d0 + 1) * HW + rl] = o[di][1] * oss[0];
            ob[(size_t)d0 * HW + rh]       = o[di][2] * oss[1];
            ob[(size_t)(d0 + 1) * HW + rh] = o[di][3] * oss[1];
        }
    }

    // ---- merge top-2 across the 4 quad lanes of each row ----
    #pragma unroll
    for (int s = 0; s < 2; s++) {
        #pragma unroll
        for (int off = 1; off <= 2; off++) {
            float om1 = __shfl_xor_sync(FULL, m1[s], off);
            int   oi1 = __shfl_xor_sync(FULL, i1[s], off);
            float om2 = __shfl_xor_sync(FULL, m2[s], off);
            int   oi2 = __shfl_xor_sync(FULL, i2[s], off);
            if (om1 > m1[s] || (om1 == m1[s] && oi1 < i1[s])) {
                float tm = m1[s]; int ti = i1[s];
                m1[s] = om1; i1[s] = oi1;
                om1 = tm; oi1 = ti;
            }
            if (om1 > m2[s] || (om1 == m2[s] && oi1 < i2[s])) { m2[s] = om1; i2[s] = oi1; }
            if (om2 > m2[s] || (om2 == m2[s] && oi2 < i2[s])) { m2[s] = om2; i2[s] = oi2; }
        }
    }
    if (q == 0) {
        s_cand[wrow + r][0]     = i1[0];
        s_cand[wrow + r][1]     = i2[0];
        s_cand[wrow + r + 8][0] = i1[1];
        s_cand[wrow + r + 8][1] = i2[1];
    }
    __syncthreads();

    // ---- fused exact-fp32 argmax refine: 2 threads per row ----
    {
        const int row  = tid >> 1;       // CTA-local row 0..63
        const int half = tid & 1;        // channel half
        const int c1 = s_cand[row][0], c2 = s_cand[row][1];
        const float* zb = zbase + row + (size_t)(half * 32) * HW;
        float zr[32];
        #pragma unroll
        for (int c = 0; c < 32; c++) zr[c] = zb[(size_t)c * HW];

        float bd = -1e30f; int bi = 0x7fffffff;
        #pragma unroll
        for (int k = 0; k < 2; k++) {
            int e = (k == 0) ? c1 : c2;
            const float4* er = reinterpret_cast<const float4*>(
                g_embn + (size_t)e * D + half * 32);
            float d0 = 0.f, d1 = 0.f, d2 = 0.f, d3 = 0.f;
            #pragma unroll
            for (int tq = 0; tq < 8; tq++) {
                float4 v = er[tq];
                d0 += zr[4 * tq + 0] * v.x;
                d1 += zr[4 * tq + 1] * v.y;
                d2 += zr[4 * tq + 2] * v.z;
                d3 += zr[4 * tq + 3] * v.w;
            }
            float part = (d0 + d1) + (d2 + d3);
            float dot = part + __shfl_xor_sync(FULL, part, 1);
            if (dot > bd || (dot == bd && e < bi)) { bd = dot; bi = e; }
        }
        if (half == 0) out[NZ + 1 + n0 + row] = (float)bi;
    }
    if (blockIdx.x == 0 && tid == 0) out[NZ] = 0.0f;
}

// ---------------------------------------------------------------------------
extern "C" void kernel_launch(void* const* d_in, const int* in_sizes, int n_in,
                              void* d_out, int out_size) {
    const float* z   = (const float*)d_in[0];
    const float* emb = (const float*)d_in[1];
    float* out = (float*)d_out;
    (void)in_sizes; (void)n_in; (void)out_size;

    prep_kernel<<<N_E / 4, 128>>>(emb);
    svq_main_kernel<<<CTAS, THREADS>>>(z, out);
}

// round 17
// speedup vs baseline: 1.0523x; 1.0523x over previous
#include <cuda_runtime.h>
#include <cuda_bf16.h>
#include <math.h>
#include <stdint.h>

// ============================================================================
// SoftVectorQuantizer via mma.sync fp16 (m16n8k16, fp32 accum), flash-style.
// z[8,64,64,64] f32, embedding[4096,64] f32.
// out = concat(z_q[2097152], entropy(=0), indices[32768] as f32)
//
// R15 (124.9us) + per-step critical-path surgery:
//  - GEMM1 accumulator chains split 4-deep -> 2x 2-deep + FADD merge
//  - all 16 movmatrix hoisted right after GEMM1 (execute in the exp/MUFU
//    latency shadow instead of serializing before GEMM2)
// Unchanged from R15: barrier-free LDG-streamed K fragments (double-buffered),
// movm-derived V (never materialized), ex2.approx.f16x2 with shift m=0.6,
// 512 CTAs x 128 thr, 16 rows/warp, 4 CTAs/SM, fp16 top-2 + exact refine.
// ============================================================================

#define N_E     4096
#define D       64
#define HW      4096
#define NZ      2097152
#define NROWS   32768
#define CTAS    512          // 64 rows per CTA
#define THREADS 128          // 4 warps x 16 rows
#define NT      64           // embedding tiles of 64
#define NSTEP   256          // NT * 4 pi-groups
#define CE      20.60992529f // log2(e)/0.07
#define CM      12.36595517f // 0.6 * CE  (softmax shift m = 0.6)

__device__ float    g_embn[N_E * D];      // normalized embedding (refine)
__device__ uint32_t g_kf[NT * 2048];      // fp16 K B-frags, step-contiguous

__device__ __forceinline__ uint32_t ex2_h2(uint32_t h) {
    uint32_t r; asm("ex2.approx.f16x2 %0, %1;" : "=r"(r) : "r"(h)); return r;
}
__device__ __forceinline__ uint32_t pack_h2(float lo, float hi) {
    uint32_t r; asm("cvt.rn.f16x2.f32 %0, %1, %2;" : "=r"(r) : "f"(hi), "f"(lo));
    return r;
}
__device__ __forceinline__ uint32_t movm_t(uint32_t s) {
    uint32_t d;
    asm("movmatrix.sync.aligned.m8n8.trans.b16 %0, %1;" : "=r"(d) : "r"(s));
    return d;
}
__device__ __forceinline__ void mma_f16(float c[4], const uint32_t a[4],
                                        uint32_t b0, uint32_t b1) {
    asm volatile(
        "mma.sync.aligned.m16n8k16.row.col.f32.f16.f16.f32 "
        "{%0,%1,%2,%3},{%4,%5,%6,%7},{%8,%9},{%0,%1,%2,%3};"
        : "+f"(c[0]), "+f"(c[1]), "+f"(c[2]), "+f"(c[3])
        : "r"(a[0]), "r"(a[1]), "r"(a[2]), "r"(a[3]), "r"(b0), "r"(b1));
}

// K-frag half-index: step s=(tile*4+pi) occupies uint4 range [s*128, s*128+128).
// uint4 j in 0..3 at [s*128 + j*32 + lane] = b-regs for (nih=j>>1, kp=j&1).
__device__ __forceinline__ int kf_hidx(int e, int d) {
    return ((((e >> 3) * 2 + (d >> 5)) * 32 + (e & 7) * 4 + ((d >> 1) & 3)) * 8)
           + ((d >> 4) & 1) * 4 + ((d >> 3) & 1) * 2 + (d & 1);
}
__device__ __forceinline__ uint32_t comp4(const uint4& v, int c) {
    return (c & 2) ? ((c & 1) ? v.w : v.z) : ((c & 1) ? v.y : v.x);
}

// ---------------------------------------------------------------------------
// prep: normalize embedding rows + scatter fp16 K B-fragments (once)
// ---------------------------------------------------------------------------
__global__ void prep_kernel(const float* __restrict__ emb) {
    int e = blockIdx.x * 4 + (threadIdx.x >> 5);
    int lane = threadIdx.x & 31;
    float2 v = reinterpret_cast<const float2*>(emb + (size_t)e * D)[lane];
    float s = v.x * v.x + v.y * v.y;
    #pragma unroll
    for (int o = 16; o; o >>= 1) s += __shfl_xor_sync(0xffffffffu, s, o);
    float inv = 1.0f / fmaxf(sqrtf(s), 1e-12f);
    float2 r; r.x = v.x * inv; r.y = v.y * inv;
    reinterpret_cast<float2*>(g_embn + (size_t)e * D)[lane] = r;

    int tile = e >> 6, el = e & 63;
    __half h0 = __float2half_rn(r.x), h1 = __float2half_rn(r.y);
    uint16_t u0 = *reinterpret_cast<uint16_t*>(&h0);
    uint16_t u1 = *reinterpret_cast<uint16_t*>(&h1);
    g_kf[tile * 2048 + (kf_hidx(el, 2 * lane) >> 1)] =
        (uint32_t)u0 | ((uint32_t)u1 << 16);
}

// ---------------------------------------------------------------------------
// main fused kernel (barrier-free mainloop, LDG-streamed K)
// ---------------------------------------------------------------------------
__global__ void __launch_bounds__(THREADS, 4)
svq_main_kernel(const float* __restrict__ z, float* __restrict__ out) {
    __shared__ int s_cand[64][2];  // argmax candidates (epilogue only)

    const int tid  = threadIdx.x;
    const int w    = tid >> 5;
    const int lane = tid & 31;
    const int q    = lane & 3;
    const int r    = lane >> 2;
    const unsigned FULL = 0xffffffffu;

    const uint4* gkl = reinterpret_cast<const uint4*>(g_kf) + lane;

    // ---- prefetch step 0 into buffer 0 (overlaps the whole Q prologue) ----
    uint4 buf[2][4];
    #pragma unroll
    for (int j = 0; j < 4; j++) buf[0][j] = gkl[j * 32];

    // ---- Q: 16 rows/warp, l2-normalize, fp16 A-frags ----
    const int n0  = blockIdx.x * 64;          // first row of this CTA
    const int bb  = n0 >> 12;
    const int hw0 = n0 & (HW - 1);
    const float* zbase = z + (size_t)bb * D * HW + hw0;
    const int wrow = w * 16;                  // warp's first row (CTA-local)

    uint32_t qa[4][4];
    {
        float zq[4][4][2];
        float ssq[2] = {0.f, 0.f};
        #pragma unroll
        for (int ks = 0; ks < 4; ks++)
            #pragma unroll
            for (int a = 0; a < 4; a++) {
                int row = wrow + r + (a & 1) * 8;
                int k   = ks * 16 + 2 * q + ((a & 2) ? 8 : 0);
                float v0 = zbase[(size_t)k * HW + row];
                float v1 = zbase[(size_t)(k + 1) * HW + row];
                zq[ks][a][0] = v0;
                zq[ks][a][1] = v1;
                ssq[a & 1] += v0 * v0 + v1 * v1;
            }
        #pragma unroll
        for (int s = 0; s < 2; s++) {
            ssq[s] += __shfl_xor_sync(FULL, ssq[s], 1);
            ssq[s] += __shfl_xor_sync(FULL, ssq[s], 2);
            ssq[s] = 1.0f / fmaxf(sqrtf(ssq[s]), 1e-12f);
        }
        #pragma unroll
        for (int ks = 0; ks < 4; ks++)
            #pragma unroll
            for (int a = 0; a < 4; a++) {
                float sc = ssq[a & 1];
                qa[ks][a] = pack_h2(zq[ks][a][0] * sc, zq[ks][a][1] * sc);
            }
    }

    float o[8][4];
    #pragma unroll
    for (int di = 0; di < 8; di++)
        #pragma unroll
        for (int c = 0; c < 4; c++) o[di][c] = 0.f;
    float m1[2] = {-1e30f, -1e30f}, m2[2] = {-1e30f, -1e30f};
    int   i1[2] = {0, 0}, i2[2] = {0, 0};

    // ---- barrier-free mainloop: 256 pi-steps, double-buffered LDG stream ----
    #pragma unroll 2
    for (int step = 0; step < NSTEP; step++) {
        const int cur = step & 1, nxt = cur ^ 1;

        // prefetch next step's 4 uint4 (clamped; last iteration re-loads 255)
        {
            int pfs = (step < NSTEP - 1) ? step + 1 : step;
            const uint4* src = gkl + pfs * 128;
            #pragma unroll
            for (int j = 0; j < 4; j++) buf[nxt][j] = src[j * 32];
        }

        // GEMM1: split accumulator chains (2-deep each) for shorter latency
        float sA[2][4], sB[2][4];
        #pragma unroll
        for (int nih = 0; nih < 2; nih++) {
            #pragma unroll
            for (int c = 0; c < 4; c++) { sA[nih][c] = 0.f; sB[nih][c] = 0.f; }
            mma_f16(sA[nih], qa[0], buf[cur][nih * 2].x, buf[cur][nih * 2].y);
            mma_f16(sB[nih], qa[2], buf[cur][nih * 2 + 1].x, buf[cur][nih * 2 + 1].y);
            mma_f16(sA[nih], qa[1], buf[cur][nih * 2].z, buf[cur][nih * 2].w);
            mma_f16(sB[nih], qa[3], buf[cur][nih * 2 + 1].z, buf[cur][nih * 2 + 1].w);
        }

        // hoisted movmatrix: V b-regs from already-arrived K regs; executes on
        // the LDSM pipe while the exp chain below waits on FMA/MUFU latency
        uint32_t vt[16];
        #pragma unroll
        for (int di = 0; di < 8; di++) {
            vt[di * 2]     = movm_t(comp4(buf[cur][di >> 2], di & 3));
            vt[di * 2 + 1] = movm_t(comp4(buf[cur][2 + (di >> 2)], di & 3));
        }

        // merge chains + exp (f16x2, shift m=0.6) + top-2
        float s[2][4];
        uint32_t a[4];
        #pragma unroll
        for (int nih = 0; nih < 2; nih++) {
            #pragma unroll
            for (int c = 0; c < 4; c++) s[nih][c] = sA[nih][c] + sB[nih][c];
            float t0 = fmaf(s[nih][0], CE, -CM);
            float t1 = fmaf(s[nih][1], CE, -CM);
            float t2 = fmaf(s[nih][2], CE, -CM);
            float t3 = fmaf(s[nih][3], CE, -CM);
            a[nih * 2 + 0] = ex2_h2(pack_h2(t0, t1));
            a[nih * 2 + 1] = ex2_h2(pack_h2(t2, t3));
        }

        // GEMM2: O += P(k16=e) * V (operands ready in vt)
        #pragma unroll
        for (int di = 0; di < 8; di++)
            mma_f16(o[di], a, vt[di * 2], vt[di * 2 + 1]);

        // top-2 tracking, gated by pair-max (off the critical path)
        #pragma unroll
        for (int nih = 0; nih < 2; nih++)
            #pragma unroll
            for (int slot = 0; slot < 2; slot++) {
                float s0 = s[nih][slot * 2], s1 = s[nih][slot * 2 + 1];
                if (fmaxf(s0, s1) > m2[slot]) {
                    int col0 = step * 16 + nih * 8 + 2 * q;
                    if (s0 > m2[slot]) {
                        if (s0 > m1[slot]) {
                            m2[slot] = m1[slot]; i2[slot] = i1[slot];
                            m1[slot] = s0;       i1[slot] = col0;
                        } else { m2[slot] = s0; i2[slot] = col0; }
                    }
                    if (s1 > m2[slot]) {
                        if (s1 > m1[slot]) {
                            m2[slot] = m1[slot]; i2[slot] = i1[slot];
                            m1[slot] = s1;       i1[slot] = col0 + 1;
                        } else { m2[slot] = s1; i2[slot] = col0 + 1; }
                    }
                }
            }
    }

    // ---- O: per-row l2norm + store ----
    {
        float oss[2] = {0.f, 0.f};
        #pragma unroll
        for (int di = 0; di < 8; di++) {
            oss[0] += o[di][0] * o[di][0] + o[di][1] * o[di][1];
            oss[1] += o[di][2] * o[di][2] + o[di][3] * o[di][3];
        }
        #pragma unroll
        for (int s = 0; s < 2; s++) {
            oss[s] += __shfl_xor_sync(FULL, oss[s], 1);
            oss[s] += __shfl_xor_sync(FULL, oss[s], 2);
            oss[s] = 1.0f / fmaxf(sqrtf(oss[s]), 1e-12f);
        }
        float* ob = out + (size_t)bb * D * HW + hw0;
        #pragma unroll
        for (int di = 0; di < 8; di++) {
            int d0 = di * 8 + 2 * q;
            int rl = wrow + r, rh = rl + 8;
            ob[(size_t)d0 * HW + rl]       = o[di][0] * oss[0];
            ob[(size_t)(d0 + 1) * HW + rl] = o[di][1] * oss[0];
            ob[(size_t)d0 * HW + rh]       = o[di][2] * oss[1];
            ob[(size_t)(d0 + 1) * HW + rh] = o[di][3] * oss[1];
        }
    }

    // ---- merge top-2 across the 4 quad lanes of each row ----
    #pragma unroll
    for (int s = 0; s < 2; s++) {
        #pragma unroll
        for (int off = 1; off <= 2; off++) {
            float om1 = __shfl_xor_sync(FULL, m1[s], off);
            int   oi1 = __shfl_xor_sync(FULL, i1[s], off);
            float om2 = __shfl_xor_sync(FULL, m2[s], off);
            int   oi2 = __shfl_xor_sync(FULL, i2[s], off);
            if (om1 > m1[s] || (om1 == m1[s] && oi1 < i1[s])) {
                float tm = m1[s]; int ti = i1[s];
                m1[s] = om1; i1[s] = oi1;
                om1 = tm; oi1 = ti;
            }
            if (om1 > m2[s] || (om1 == m2[s] && oi1 < i2[s])) { m2[s] = om1; i2[s] = oi1; }
            if (om2 > m2[s] || (om2 == m2[s] && oi2 < i2[s])) { m2[s] = om2; i2[s] = oi2; }
        }
    }
    if (q == 0) {
        s_cand[wrow + r][0]     = i1[0];
        s_cand[wrow + r][1]     = i2[0];
        s_cand[wrow + r + 8][0] = i1[1];
        s_cand[wrow + r + 8][1] = i2[1];
    }
    __syncthreads();

    // ---- fused exact-fp32 argmax refine: 2 threads per row ----
    {
        const int row  = tid >> 1;       // CTA-local row 0..63
        const int half = tid & 1;        // channel half
        const int c1 = s_cand[row][0], c2 = s_cand[row][1];
        const float* zb = zbase + row + (size_t)(half * 32) * HW;
        float zr[32];
        #pragma unroll
        for (int c = 0; c < 32; c++) zr[c] = zb[(size_t)c * HW];

        float bd = -1e30f; int bi = 0x7fffffff;
        #pragma unroll
        for (int k = 0; k < 2; k++) {
            int e = (k == 0) ? c1 : c2;
            const float4* er = reinterpret_cast<const float4*>(
                g_embn + (size_t)e * D + half * 32);
            float d0 = 0.f, d1 = 0.f, d2 = 0.f, d3 = 0.f;
            #pragma unroll
            for (int tq = 0; tq < 8; tq++) {
                float4 v = er[tq];
                d0 += zr[4 * tq + 0] * v.x;
                d1 += zr[4 * tq + 1] * v.y;
                d2 += zr[4 * tq + 2] * v.z;
                d3 += zr[4 * tq + 3] * v.w;
            }
            float part = (d0 + d1) + (d2 + d3);
            float dot = part + __shfl_xor_sync(FULL, part, 1);
            if (dot > bd || (dot == bd && e < bi)) { bd = dot; bi = e; }
        }
        if (half == 0) out[NZ + 1 + n0 + row] = (float)bi;
    }
    if (blockIdx.x == 0 && tid == 0) out[NZ] = 0.0f;
}

// ---------------------------------------------------------------------------
extern "C" void kernel_launch(void* const* d_in, const int* in_sizes, int n_in,
                              void* d_out, int out_size) {
    const float* z   = (const float*)d_in[0];
    const float* emb = (const float*)d_in[1];
    float* out = (float*)d_out;
    (void)in_sizes; (void)n_in; (void)out_size;

    prep_kernel<<<N_E / 4, 128>>>(emb);
    svq_main_kernel<<<CTAS, THREADS>>>(z, out);
}